// round 1
// baseline (speedup 1.0000x reference)
#include <cuda_runtime.h>
#include <math.h>

#define NB 4096

// ---------------- scratch (device globals; no allocation allowed) ----------------
__device__ float g_h1[NB * 32 * 196];   // conv1 out [B,32,14,14]
__device__ float g_h2[NB * 32 * 49];    // conv2 out [B,32,7,7]
__device__ float g_h3[NB * 1024];       // conv3 out [B,64,4,4] flattened
__device__ float g_hf[NB * 256];        // fc1 out
__device__ float g_z [NB * 20];         // zlat
__device__ float g_f2[NB * 256];        // fc2 out
__device__ float g_f3[NB * 1024];       // fc3 out [B,64,4,4]
__device__ float g_u1[NB * 32 * 49];    // deconv1 out [B,32,7,7]
__device__ float g_u2[NB * 32 * 196];   // deconv2 out [B,32,14,14]

#define XHAT_N   (NB * 784)
#define MU_OFF   (NB * 784)
#define LS_OFF   (NB * 784 + NB * 20)

// ---------------- conv1: [B,1,28,28] -> [B,32,14,14], k4 s2 p1, relu ----------------
__global__ void conv1_k(const float* __restrict__ x, const float* __restrict__ w,
                        const float* __restrict__ bias) {
    extern __shared__ float sm[];
    float* in_s = sm;          // 784
    float* w_s  = sm + 784;    // 512, layout [kk][oc]
    int b = blockIdx.x, tid = threadIdx.x;
    const float* xin = x + b * 784;
    for (int i = tid; i < 784; i += 256) in_s[i] = xin[i];
    for (int i = tid; i < 512; i += 256) { int oc = i & 31, kk = i >> 5; w_s[kk * 32 + oc] = w[oc * 16 + kk]; }
    __syncthreads();
    const float4* w4 = (const float4*)w_s;
    for (int u = tid; u < 784; u += 256) {
        int p = u >> 2, g = u & 3;
        int oy = p / 14, ox = p % 14;
        float acc[8];
        #pragma unroll
        for (int j = 0; j < 8; j++) acc[j] = bias[g * 8 + j];
        #pragma unroll
        for (int ky = 0; ky < 4; ky++) {
            int iy = oy * 2 - 1 + ky;
            if (iy < 0 || iy >= 28) continue;
            #pragma unroll
            for (int kx = 0; kx < 4; kx++) {
                int ix = ox * 2 - 1 + kx;
                if (ix < 0 || ix >= 28) continue;
                float xv = in_s[iy * 28 + ix];
                int wb = ((ky * 4 + kx) * 32 + g * 8) >> 2;
                float4 wa = w4[wb], wc = w4[wb + 1];
                acc[0] += xv * wa.x; acc[1] += xv * wa.y; acc[2] += xv * wa.z; acc[3] += xv * wa.w;
                acc[4] += xv * wc.x; acc[5] += xv * wc.y; acc[6] += xv * wc.z; acc[7] += xv * wc.w;
            }
        }
        #pragma unroll
        for (int j = 0; j < 8; j++)
            g_h1[(size_t)(b * 32 + g * 8 + j) * 196 + p] = fmaxf(acc[j], 0.f);
    }
}

// ---------------- conv2: [B,32,14,14] -> [B,32,7,7], k4 s2 p1, relu ----------------
__global__ void conv2_k(const float* __restrict__ w, const float* __restrict__ bias) {
    extern __shared__ float sm[];
    float* in_s = sm;            // 6272
    float* w_s  = sm + 6272;     // 16384, [ic*16+kk][oc]
    int b = blockIdx.x, tid = threadIdx.x;
    const float* xin = g_h1 + (size_t)b * 6272;
    for (int i = tid; i < 6272; i += 256) in_s[i] = xin[i];
    for (int i = tid; i < 16384; i += 256) { int oc = i & 31, rest = i >> 5; w_s[i] = w[oc * 512 + rest]; }
    __syncthreads();
    const float4* w4 = (const float4*)w_s;
    if (tid < 196) {
        int p = tid >> 2, g = tid & 3;
        int oy = p / 7, ox = p % 7;
        float acc[8];
        #pragma unroll
        for (int j = 0; j < 8; j++) acc[j] = bias[g * 8 + j];
        for (int ic = 0; ic < 32; ic++) {
            #pragma unroll
            for (int ky = 0; ky < 4; ky++) {
                int iy = oy * 2 - 1 + ky;
                if (iy < 0 || iy >= 14) continue;
                #pragma unroll
                for (int kx = 0; kx < 4; kx++) {
                    int ix = ox * 2 - 1 + kx;
                    if (ix < 0 || ix >= 14) continue;
                    float xv = in_s[ic * 196 + iy * 14 + ix];
                    int wb = ((ic * 16 + ky * 4 + kx) * 32 + g * 8) >> 2;
                    float4 wa = w4[wb], wc = w4[wb + 1];
                    acc[0] += xv * wa.x; acc[1] += xv * wa.y; acc[2] += xv * wa.z; acc[3] += xv * wa.w;
                    acc[4] += xv * wc.x; acc[5] += xv * wc.y; acc[6] += xv * wc.z; acc[7] += xv * wc.w;
                }
            }
        }
        #pragma unroll
        for (int j = 0; j < 8; j++)
            g_h2[(size_t)(b * 32 + g * 8 + j) * 49 + p] = fmaxf(acc[j], 0.f);
    }
}

// ---------------- conv3: [B,32,7,7] -> [B,64,4,4], k3 s2 p1, relu ----------------
__global__ void conv3_k(const float* __restrict__ w, const float* __restrict__ bias) {
    extern __shared__ float sm[];
    float* in_s = sm;           // 1568
    float* w_s  = sm + 1568;    // 18432, [ic*9+kk][oc]
    int b = blockIdx.x, tid = threadIdx.x;
    const float* xin = g_h2 + (size_t)b * 1568;
    for (int i = tid; i < 1568; i += 128) in_s[i] = xin[i];
    for (int i = tid; i < 18432; i += 128) { int oc = i & 63, rest = i >> 6; w_s[i] = w[oc * 288 + rest]; }
    __syncthreads();
    const float4* w4 = (const float4*)w_s;
    int p = tid >> 3, g = tid & 7;     // 16 spatial x 8 groups = 128 threads
    int oy = p >> 2, ox = p & 3;
    float acc[8];
    #pragma unroll
    for (int j = 0; j < 8; j++) acc[j] = bias[g * 8 + j];
    for (int ic = 0; ic < 32; ic++) {
        #pragma unroll
        for (int ky = 0; ky < 3; ky++) {
            int iy = oy * 2 - 1 + ky;
            if (iy < 0 || iy >= 7) continue;
            #pragma unroll
            for (int kx = 0; kx < 3; kx++) {
                int ix = ox * 2 - 1 + kx;
                if (ix < 0 || ix >= 7) continue;
                float xv = in_s[ic * 49 + iy * 7 + ix];
                int wb = ((ic * 9 + ky * 3 + kx) * 64 + g * 8) >> 2;
                float4 wa = w4[wb], wc = w4[wb + 1];
                acc[0] += xv * wa.x; acc[1] += xv * wa.y; acc[2] += xv * wa.z; acc[3] += xv * wa.w;
                acc[4] += xv * wc.x; acc[5] += xv * wc.y; acc[6] += xv * wc.z; acc[7] += xv * wc.w;
            }
        }
    }
    #pragma unroll
    for (int j = 0; j < 8; j++)
        g_h3[(size_t)(b * 64 + g * 8 + j) * 16 + p] = fmaxf(acc[j], 0.f);
}

// ---------------- generic NT GEMM: C[m,n] = act(sum_k A[m,k]*W[n,k] + bias[n]) ----------------
// BM=BN=64, BK=16, 256 threads, 4x4 micro-tile. M,N mult of 64; K mult of 16.
__global__ void gemm_k(const float* __restrict__ A, const float* __restrict__ W,
                       const float* __restrict__ bias, float* __restrict__ C,
                       int M, int N, int K, int relu) {
    __shared__ float As[16 * 68];
    __shared__ float Ws[16 * 68];
    int tid = threadIdx.x, tx = tid & 15, ty = tid >> 4;
    int m0 = blockIdx.y * 64, n0 = blockIdx.x * 64;
    float acc[4][4] = {};
    for (int kt = 0; kt < K; kt += 16) {
        #pragma unroll
        for (int i = 0; i < 4; i++) {
            int idx = tid + i * 256;
            int k = idx & 15, m = idx >> 4;
            As[k * 68 + m] = A[(size_t)(m0 + m) * K + kt + k];
            Ws[k * 68 + m] = W[(size_t)(n0 + m) * K + kt + k];
        }
        __syncthreads();
        #pragma unroll
        for (int kk = 0; kk < 16; kk++) {
            float4 a  = *(const float4*)&As[kk * 68 + ty * 4];
            float4 bv = *(const float4*)&Ws[kk * 68 + tx * 4];
            float av[4] = {a.x, a.y, a.z, a.w};
            float bb[4] = {bv.x, bv.y, bv.z, bv.w};
            #pragma unroll
            for (int i = 0; i < 4; i++)
                #pragma unroll
                for (int j = 0; j < 4; j++) acc[i][j] += av[i] * bb[j];
        }
        __syncthreads();
    }
    #pragma unroll
    for (int i = 0; i < 4; i++) {
        int m = m0 + ty * 4 + i;
        #pragma unroll
        for (int j = 0; j < 4; j++) {
            int n = n0 + tx * 4 + j;
            float v = acc[i][j] + bias[n];
            if (relu) v = fmaxf(v, 0.f);
            C[(size_t)m * N + n] = v;
        }
    }
}

// ---------------- mu / logvar / 100-step reversal / reparameterize ----------------
__global__ void latent_k(const float* __restrict__ w_mu, const float* __restrict__ b_mu,
                         const float* __restrict__ w_ls, const float* __restrict__ b_ls,
                         const float* __restrict__ eps, float* __restrict__ out) {
    int idx = blockIdx.x * 256 + threadIdx.x;
    if (idx >= NB * 20) return;
    int b = idx / 20, l = idx % 20;
    const float4* h4 = (const float4*)(g_hf + (size_t)b * 256);
    const float4* wm = (const float4*)(w_mu + (size_t)l * 256);
    const float4* wl = (const float4*)(w_ls + (size_t)l * 256);
    float sm_ = 0.f, sl_ = 0.f;
    #pragma unroll 8
    for (int k = 0; k < 64; k++) {
        float4 h = h4[k], a = wm[k], c = wl[k];
        sm_ += h.x * a.x + h.y * a.y + h.z * a.z + h.w * a.w;
        sl_ += h.x * c.x + h.y * c.y + h.z * c.z + h.w * c.w;
    }
    float mu = sm_ + b_mu[l];
    float ls = sl_ + b_ls[l];
    out[MU_OFF + idx] = mu;
    out[LS_OFF + idx] = ls;
    float m = mu, s = ls;
    #pragma unroll 4
    for (int i = 0; i < 100; i++) {
        m = m + 0.1f * m;
        s = s + 0.05f * (expf(s) - 1.0f);
    }
    g_z[idx] = eps[idx] * expf(0.5f * s) + m;
}

// ---------------- fc2: [B,20] -> [B,256], relu ----------------
__global__ void fc2_k(const float* __restrict__ w, const float* __restrict__ bias) {
    int idx = blockIdx.x * 256 + threadIdx.x;
    if (idx >= NB * 256) return;
    int b = idx >> 8, o = idx & 255;
    const float* z = g_z + (size_t)b * 20;
    const float* wr = w + (size_t)o * 20;
    float acc = bias[o];
    #pragma unroll
    for (int k = 0; k < 20; k++) acc += z[k] * wr[k];
    g_f2[idx] = fmaxf(acc, 0.f);
}

// ---------------- deconv1: [B,64,4,4] -> [B,32,7,7], k3 s2 p1, relu ----------------
__global__ void deconv1_k(const float* __restrict__ w, const float* __restrict__ bias) {
    extern __shared__ float sm[];
    float* in_s = sm;           // 1024
    float* w_s  = sm + 1024;    // 18432, [ic*9+kk][oc]
    int b = blockIdx.x, tid = threadIdx.x;
    const float* xin = g_f3 + (size_t)b * 1024;
    for (int i = tid; i < 1024; i += 256) in_s[i] = xin[i];
    for (int i = tid; i < 18432; i += 256) {
        int oc = i & 31, rest = i >> 5;
        int ic = rest / 9, kk = rest % 9;
        w_s[i] = w[ic * 288 + oc * 9 + kk];
    }
    __syncthreads();
    const float4* w4 = (const float4*)w_s;
    if (tid < 196) {
        int p = tid >> 2, g = tid & 3;
        int oy = p / 7, ox = p % 7;
        float acc[8];
        #pragma unroll
        for (int j = 0; j < 8; j++) acc[j] = bias[g * 8 + j];
        #pragma unroll
        for (int ky = 0; ky < 3; ky++) {
            int t = oy + 1 - ky;
            if (t < 0 || (t & 1)) continue;
            int iy = t >> 1; if (iy >= 4) continue;
            #pragma unroll
            for (int kx = 0; kx < 3; kx++) {
                int u2 = ox + 1 - kx;
                if (u2 < 0 || (u2 & 1)) continue;
                int ix = u2 >> 1; if (ix >= 4) continue;
                for (int ic = 0; ic < 64; ic++) {
                    float xv = in_s[ic * 16 + iy * 4 + ix];
                    int wb = ((ic * 9 + ky * 3 + kx) * 32 + g * 8) >> 2;
                    float4 wa = w4[wb], wc = w4[wb + 1];
                    acc[0] += xv * wa.x; acc[1] += xv * wa.y; acc[2] += xv * wa.z; acc[3] += xv * wa.w;
                    acc[4] += xv * wc.x; acc[5] += xv * wc.y; acc[6] += xv * wc.z; acc[7] += xv * wc.w;
                }
            }
        }
        #pragma unroll
        for (int j = 0; j < 8; j++)
            g_u1[(size_t)(b * 32 + g * 8 + j) * 49 + p] = fmaxf(acc[j], 0.f);
    }
}

// ---------------- deconv2: [B,32,7,7] -> [B,32,14,14], k4 s2 p1, relu ----------------
__global__ void deconv2_k(const float* __restrict__ w, const float* __restrict__ bias) {
    extern __shared__ float sm[];
    float* in_s = sm;           // 1568
    float* w_s  = sm + 1568;    // 16384, [ic*16+kk][oc]
    int b = blockIdx.x, tid = threadIdx.x;
    const float* xin = g_u1 + (size_t)b * 1568;
    for (int i = tid; i < 1568; i += 256) in_s[i] = xin[i];
    for (int i = tid; i < 16384; i += 256) {
        int oc = i & 31, rest = i >> 5;
        w_s[i] = w[(rest >> 4) * 512 + oc * 16 + (rest & 15)];
    }
    __syncthreads();
    const float4* w4 = (const float4*)w_s;
    for (int u = tid; u < 784; u += 256) {
        int p = u >> 2, g = u & 3;
        int oy = p / 14, ox = p % 14;
        float acc[8];
        #pragma unroll
        for (int j = 0; j < 8; j++) acc[j] = bias[g * 8 + j];
        #pragma unroll
        for (int ky = 0; ky < 4; ky++) {
            int t = oy + 1 - ky;
            if (t < 0 || (t & 1)) continue;
            int iy = t >> 1; if (iy >= 7) continue;
            #pragma unroll
            for (int kx = 0; kx < 4; kx++) {
                int u2 = ox + 1 - kx;
                if (u2 < 0 || (u2 & 1)) continue;
                int ix = u2 >> 1; if (ix >= 7) continue;
                for (int ic = 0; ic < 32; ic++) {
                    float xv = in_s[ic * 49 + iy * 7 + ix];
                    int wb = ((ic * 16 + ky * 4 + kx) * 32 + g * 8) >> 2;
                    float4 wa = w4[wb], wc = w4[wb + 1];
                    acc[0] += xv * wa.x; acc[1] += xv * wa.y; acc[2] += xv * wa.z; acc[3] += xv * wa.w;
                    acc[4] += xv * wc.x; acc[5] += xv * wc.y; acc[6] += xv * wc.z; acc[7] += xv * wc.w;
                }
            }
        }
        #pragma unroll
        for (int j = 0; j < 8; j++)
            g_u2[(size_t)(b * 32 + g * 8 + j) * 196 + p] = fmaxf(acc[j], 0.f);
    }
}

// ---------------- deconv3: [B,32,14,14] -> [B,1,28,28], k4 s2 p1, sigmoid ----------------
__global__ void deconv3_k(const float* __restrict__ w, const float* __restrict__ bias,
                          float* __restrict__ out) {
    extern __shared__ float sm[];
    float* in_s = sm;           // 6272
    float* w_s  = sm + 6272;    // 512 [ic][kk]
    int b = blockIdx.x, tid = threadIdx.x;
    const float* xin = g_u2 + (size_t)b * 6272;
    for (int i = tid; i < 6272; i += 256) in_s[i] = xin[i];
    for (int i = tid; i < 512; i += 256) w_s[i] = w[i];
    __syncthreads();
    float b0 = bias[0];
    for (int u = tid; u < 784; u += 256) {
        int oy = u / 28, ox = u % 28;
        float acc = b0;
        #pragma unroll
        for (int ky = 0; ky < 4; ky++) {
            int t = oy + 1 - ky;
            if (t < 0 || (t & 1)) continue;
            int iy = t >> 1; if (iy >= 14) continue;
            #pragma unroll
            for (int kx = 0; kx < 4; kx++) {
                int u2 = ox + 1 - kx;
                if (u2 < 0 || (u2 & 1)) continue;
                int ix = u2 >> 1; if (ix >= 14) continue;
                for (int ic = 0; ic < 32; ic++)
                    acc += in_s[ic * 196 + iy * 14 + ix] * w_s[ic * 16 + ky * 4 + kx];
            }
        }
        out[(size_t)b * 784 + u] = 1.0f / (1.0f + expf(-acc));
    }
}

// ---------------- launch ----------------
extern "C" void kernel_launch(void* const* d_in, const int* in_sizes, int n_in,
                              void* d_out, int out_size) {
    const float* x     = (const float*)d_in[0];
    const float* eps   = (const float*)d_in[1];
    const float* w_c1  = (const float*)d_in[2];
    const float* b_c1  = (const float*)d_in[3];
    const float* w_c2  = (const float*)d_in[4];
    const float* b_c2  = (const float*)d_in[5];
    const float* w_c3  = (const float*)d_in[6];
    const float* b_c3  = (const float*)d_in[7];
    const float* w_fc1 = (const float*)d_in[8];
    const float* b_fc1 = (const float*)d_in[9];
    const float* w_mu  = (const float*)d_in[10];
    const float* b_mu  = (const float*)d_in[11];
    const float* w_ls  = (const float*)d_in[12];
    const float* b_ls  = (const float*)d_in[13];
    const float* w_fc2 = (const float*)d_in[14];
    const float* b_fc2 = (const float*)d_in[15];
    const float* w_fc3 = (const float*)d_in[16];
    const float* b_fc3 = (const float*)d_in[17];
    const float* w_d1  = (const float*)d_in[18];
    const float* b_d1  = (const float*)d_in[19];
    const float* w_d2  = (const float*)d_in[20];
    const float* b_d2  = (const float*)d_in[21];
    const float* w_d3  = (const float*)d_in[22];
    const float* b_d3  = (const float*)d_in[23];
    float* out = (float*)d_out;

    // dynamic smem limits (>48KB kernels); attribute set is not a stream op -> capture-safe
    cudaFuncSetAttribute(conv2_k,   cudaFuncAttributeMaxDynamicSharedMemorySize, 90624);
    cudaFuncSetAttribute(conv3_k,   cudaFuncAttributeMaxDynamicSharedMemorySize, 80000);
    cudaFuncSetAttribute(deconv1_k, cudaFuncAttributeMaxDynamicSharedMemorySize, 77824);
    cudaFuncSetAttribute(deconv2_k, cudaFuncAttributeMaxDynamicSharedMemorySize, 71808);

    float *p_h3, *p_hf, *p_f2, *p_f3;
    cudaGetSymbolAddress((void**)&p_h3, g_h3);
    cudaGetSymbolAddress((void**)&p_hf, g_hf);
    cudaGetSymbolAddress((void**)&p_f2, g_f2);
    cudaGetSymbolAddress((void**)&p_f3, g_f3);

    conv1_k<<<NB, 256, (784 + 512) * 4>>>(x, w_c1, b_c1);
    conv2_k<<<NB, 256, 90624>>>(w_c2, b_c2);
    conv3_k<<<NB, 128, 80000>>>(w_c3, b_c3);
    gemm_k<<<dim3(256 / 64, NB / 64), 256>>>(p_h3, w_fc1, b_fc1, p_hf, NB, 256, 1024, 1);
    latent_k<<<(NB * 20 + 255) / 256, 256>>>(w_mu, b_mu, w_ls, b_ls, eps, out);
    fc2_k<<<(NB * 256 + 255) / 256, 256>>>(w_fc2, b_fc2);
    gemm_k<<<dim3(1024 / 64, NB / 64), 256>>>(p_f2, w_fc3, b_fc3, p_f3, NB, 1024, 256, 1);
    deconv1_k<<<NB, 256, 77824>>>(w_d1, b_d1);
    deconv2_k<<<NB, 256, 71808>>>(w_d2, b_d2);
    deconv3_k<<<NB, 256, (6272 + 512) * 4>>>(w_d3, b_d3, out);
}

// round 2
// speedup vs baseline: 1.4176x; 1.4176x over previous
#include <cuda_runtime.h>
#include <math.h>

#define NB 4096

// ---------------- scratch ----------------
__device__ float g_h1[NB * 32 * 196];
__device__ float g_h2[NB * 32 * 49];
__device__ float g_h3[NB * 1024];
__device__ float g_hf[NB * 256];
__device__ float g_z [NB * 20];
__device__ float g_f2[NB * 256];
__device__ float g_f3[NB * 1024];
__device__ float g_u1[NB * 32 * 49];
__device__ float g_u2[NB * 32 * 196];

#define MU_OFF   (NB * 784)
#define LS_OFF   (NB * 784 + NB * 20)

// ---------------- conv1: [B,1,28,28] -> [B,32,14,14], k4 s2 p1, relu ----------------
__global__ void conv1_k(const float* __restrict__ x, const float* __restrict__ w,
                        const float* __restrict__ bias) {
    extern __shared__ float sm[];
    float* in_s = sm;          // 784
    float* w_s  = sm + 784;    // 512, [kk][oc]
    int b = blockIdx.x, tid = threadIdx.x;
    const float* xin = x + b * 784;
    for (int i = tid; i < 784; i += 256) in_s[i] = xin[i];
    for (int i = tid; i < 512; i += 256) { int oc = i & 31, kk = i >> 5; w_s[kk * 32 + oc] = w[oc * 16 + kk]; }
    __syncthreads();
    const float4* w4 = (const float4*)w_s;
    for (int u = tid; u < 784; u += 256) {
        int p = u >> 2, g = u & 3;
        int oy = p / 14, ox = p % 14;
        float acc[8];
        #pragma unroll
        for (int j = 0; j < 8; j++) acc[j] = bias[g * 8 + j];
        #pragma unroll
        for (int ky = 0; ky < 4; ky++) {
            int iy = oy * 2 - 1 + ky;
            if (iy < 0 || iy >= 28) continue;
            #pragma unroll
            for (int kx = 0; kx < 4; kx++) {
                int ix = ox * 2 - 1 + kx;
                if (ix < 0 || ix >= 28) continue;
                float xv = in_s[iy * 28 + ix];
                int wb = ((ky * 4 + kx) * 32 + g * 8) >> 2;
                float4 wa = w4[wb], wc = w4[wb + 1];
                acc[0] += xv * wa.x; acc[1] += xv * wa.y; acc[2] += xv * wa.z; acc[3] += xv * wa.w;
                acc[4] += xv * wc.x; acc[5] += xv * wc.y; acc[6] += xv * wc.z; acc[7] += xv * wc.w;
            }
        }
        #pragma unroll
        for (int j = 0; j < 8; j++)
            g_h1[(size_t)(b * 32 + g * 8 + j) * 196 + p] = fmaxf(acc[j], 0.f);
    }
}

// ---------------- conv2: 4 imgs/block, padded 16x16 inputs, acc[16] ----------------
// threads 416 (active 392 = 4 img * 49 pix * 2 oc-halves)
__global__ void conv2_k(const float* __restrict__ w, const float* __restrict__ bias) {
    extern __shared__ float sm[];
    float* in_s = sm;            // 4*32*256 = 32768
    float* w_s  = sm + 32768;    // 16384, [ic*16+kk][oc]
    int b0 = blockIdx.x * 4, tid = threadIdx.x, nt = blockDim.x;
    // phase 1: zero padded input + stage weights
    float4* z4 = (float4*)in_s;
    for (int i = tid; i < 8192; i += nt) z4[i] = make_float4(0.f, 0.f, 0.f, 0.f);
    for (int i = tid; i < 16384; i += nt) {
        int oc = i & 31, rest = i >> 5;
        w_s[rest * 32 + oc] = w[oc * 512 + rest];
    }
    __syncthreads();
    // phase 2: fill interior
    for (int i = tid; i < 4 * 6272; i += nt) {
        int img = i / 6272, r = i % 6272;
        int ic = r / 196, q = r % 196, y = q / 14, xx = q % 14;
        in_s[(img * 32 + ic) * 256 + (y + 1) * 16 + (xx + 1)] = g_h1[(size_t)(b0 + img) * 6272 + r];
    }
    __syncthreads();
    if (tid >= 392) return;
    int img = tid / 98, rr = tid % 98;
    int p = rr % 49, half = rr / 49;
    int oy = p / 7, ox = p % 7;
    float acc[16];
    #pragma unroll
    for (int j = 0; j < 16; j++) acc[j] = bias[half * 16 + j];
    for (int ic = 0; ic < 32; ic++) {
        const float* xs = in_s + (img * 32 + ic) * 256 + (oy * 2) * 16 + ox * 2;
        const float4* wp = (const float4*)w_s + (ic * 16) * 8 + half * 4;
        #pragma unroll
        for (int kk = 0; kk < 16; kk++) {
            float xv = xs[(kk >> 2) * 16 + (kk & 3)];
            float4 a = wp[kk * 8], b2 = wp[kk * 8 + 1], c = wp[kk * 8 + 2], d = wp[kk * 8 + 3];
            acc[0] += xv * a.x;  acc[1] += xv * a.y;  acc[2] += xv * a.z;  acc[3] += xv * a.w;
            acc[4] += xv * b2.x; acc[5] += xv * b2.y; acc[6] += xv * b2.z; acc[7] += xv * b2.w;
            acc[8] += xv * c.x;  acc[9] += xv * c.y;  acc[10] += xv * c.z; acc[11] += xv * c.w;
            acc[12] += xv * d.x; acc[13] += xv * d.y; acc[14] += xv * d.z; acc[15] += xv * d.w;
        }
    }
    #pragma unroll
    for (int j = 0; j < 16; j++)
        g_h2[(size_t)((b0 + img) * 32 + half * 16 + j) * 49 + p] = fmaxf(acc[j], 0.f);
}

// ---------------- conv3: 12 imgs/block, padded 9x9 (ch stride 84), acc[32] ----------------
// threads 384 (12 img * 16 pix * 2 halves)
__global__ void conv3_k(const float* __restrict__ w, const float* __restrict__ bias) {
    extern __shared__ float sm[];
    float* in_s = sm;            // 12*32*84 = 32256
    float* w_s  = sm + 32256;    // 18432, [ic*9+kk][oc]
    int b0 = blockIdx.x * 12, tid = threadIdx.x, nt = blockDim.x;
    int nimg = min(12, NB - b0);
    float4* z4 = (float4*)in_s;
    for (int i = tid; i < 8064; i += nt) z4[i] = make_float4(0.f, 0.f, 0.f, 0.f);
    for (int i = tid; i < 18432; i += nt) {
        int oc = i & 63, rest = i >> 6;
        w_s[rest * 64 + oc] = w[oc * 288 + rest];
    }
    __syncthreads();
    for (int i = tid; i < nimg * 1568; i += nt) {
        int img = i / 1568, r = i % 1568;
        int ic = r / 49, q = r % 49, y = q / 7, xx = q % 7;
        in_s[(img * 32 + ic) * 84 + (y + 1) * 9 + (xx + 1)] = g_h2[(size_t)(b0 + img) * 1568 + r];
    }
    __syncthreads();
    int img = tid / 32, rr = tid % 32;
    if (img >= nimg) return;
    int p = rr & 15, half = rr >> 4;
    int oy = p >> 2, ox = p & 3;
    float acc[32];
    #pragma unroll
    for (int j = 0; j < 32; j++) acc[j] = bias[half * 32 + j];
    for (int ic = 0; ic < 32; ic++) {
        const float* xs = in_s + (img * 32 + ic) * 84 + (oy * 2) * 9 + ox * 2;
        const float4* wp = (const float4*)w_s + (ic * 9) * 16 + half * 8;
        #pragma unroll
        for (int kk = 0; kk < 9; kk++) {
            float xv = xs[(kk / 3) * 9 + (kk % 3)];
            const float4* wq = wp + kk * 16;
            #pragma unroll
            for (int v = 0; v < 8; v++) {
                float4 a = wq[v];
                acc[v * 4]     += xv * a.x; acc[v * 4 + 1] += xv * a.y;
                acc[v * 4 + 2] += xv * a.z; acc[v * 4 + 3] += xv * a.w;
            }
        }
    }
    #pragma unroll
    for (int j = 0; j < 32; j++)
        g_h3[(size_t)((b0 + img) * 64 + half * 32 + j) * 16 + p] = fmaxf(acc[j], 0.f);
}

// ---------------- NT GEMM (unchanged) ----------------
__global__ void gemm_k(const float* __restrict__ A, const float* __restrict__ W,
                       const float* __restrict__ bias, float* __restrict__ C,
                       int M, int N, int K, int relu) {
    __shared__ float As[16 * 68];
    __shared__ float Ws[16 * 68];
    int tid = threadIdx.x, tx = tid & 15, ty = tid >> 4;
    int m0 = blockIdx.y * 64, n0 = blockIdx.x * 64;
    float acc[4][4] = {};
    for (int kt = 0; kt < K; kt += 16) {
        #pragma unroll
        for (int i = 0; i < 4; i++) {
            int idx = tid + i * 256;
            int k = idx & 15, m = idx >> 4;
            As[k * 68 + m] = A[(size_t)(m0 + m) * K + kt + k];
            Ws[k * 68 + m] = W[(size_t)(n0 + m) * K + kt + k];
        }
        __syncthreads();
        #pragma unroll
        for (int kk = 0; kk < 16; kk++) {
            float4 a  = *(const float4*)&As[kk * 68 + ty * 4];
            float4 bv = *(const float4*)&Ws[kk * 68 + tx * 4];
            float av[4] = {a.x, a.y, a.z, a.w};
            float bb[4] = {bv.x, bv.y, bv.z, bv.w};
            #pragma unroll
            for (int i = 0; i < 4; i++)
                #pragma unroll
                for (int j = 0; j < 4; j++) acc[i][j] += av[i] * bb[j];
        }
        __syncthreads();
    }
    #pragma unroll
    for (int i = 0; i < 4; i++) {
        int m = m0 + ty * 4 + i;
        #pragma unroll
        for (int j = 0; j < 4; j++) {
            int n = n0 + tx * 4 + j;
            float v = acc[i][j] + bias[n];
            if (relu) v = fmaxf(v, 0.f);
            C[(size_t)m * N + n] = v;
        }
    }
}

// ---------------- latent (unchanged) ----------------
__global__ void latent_k(const float* __restrict__ w_mu, const float* __restrict__ b_mu,
                         const float* __restrict__ w_ls, const float* __restrict__ b_ls,
                         const float* __restrict__ eps, float* __restrict__ out) {
    int idx = blockIdx.x * 256 + threadIdx.x;
    if (idx >= NB * 20) return;
    int b = idx / 20, l = idx % 20;
    const float4* h4 = (const float4*)(g_hf + (size_t)b * 256);
    const float4* wm = (const float4*)(w_mu + (size_t)l * 256);
    const float4* wl = (const float4*)(w_ls + (size_t)l * 256);
    float sm_ = 0.f, sl_ = 0.f;
    #pragma unroll 8
    for (int k = 0; k < 64; k++) {
        float4 h = h4[k], a = wm[k], c = wl[k];
        sm_ += h.x * a.x + h.y * a.y + h.z * a.z + h.w * a.w;
        sl_ += h.x * c.x + h.y * c.y + h.z * c.z + h.w * c.w;
    }
    float mu = sm_ + b_mu[l];
    float ls = sl_ + b_ls[l];
    out[MU_OFF + idx] = mu;
    out[LS_OFF + idx] = ls;
    float m = mu, s = ls;
    #pragma unroll 4
    for (int i = 0; i < 100; i++) {
        m = m + 0.1f * m;
        s = s + 0.05f * (expf(s) - 1.0f);
    }
    g_z[idx] = eps[idx] * expf(0.5f * s) + m;
}

// ---------------- fc2 (unchanged) ----------------
__global__ void fc2_k(const float* __restrict__ w, const float* __restrict__ bias) {
    int idx = blockIdx.x * 256 + threadIdx.x;
    if (idx >= NB * 256) return;
    int b = idx >> 8, o = idx & 255;
    const float* z = g_z + (size_t)b * 20;
    const float* wr = w + (size_t)o * 20;
    float acc = bias[o];
    #pragma unroll
    for (int k = 0; k < 20; k++) acc += z[k] * wr[k];
    g_f2[idx] = fmaxf(acc, 0.f);
}

// ---------------- deconv1: 5 imgs/block, parity taps (predicated 2x2), acc[16] ----------------
// threads 512 (active 490 = 5 img * 49 pix * 2 halves). no padding needed (all valid iy in [0,3])
__global__ void deconv1_k(const float* __restrict__ w, const float* __restrict__ bias) {
    extern __shared__ float sm[];
    float* in_s = sm;            // 5*1024
    float* w_s  = sm + 5120;     // 18432, [ic*9+kk][oc]
    int b0 = blockIdx.x * 5, tid = threadIdx.x, nt = blockDim.x;
    int nimg = min(5, NB - b0);
    for (int i = tid; i < nimg * 1024; i += nt) in_s[i] = g_f3[(size_t)b0 * 1024 + i];
    for (int i = tid; i < 18432; i += nt) {
        int oc = i & 31, rest = i >> 5;
        int ic = rest / 9, kk = rest % 9;
        w_s[rest * 32 + oc] = w[ic * 288 + oc * 9 + kk];
    }
    __syncthreads();
    if (tid >= 490) return;
    int img = tid / 98, rr = tid % 98;
    if (img >= nimg) return;
    int p = rr % 49, half = rr / 49;
    int oy = p / 7, ox = p % 7;
    // tap A always valid; tap B (k=2) valid only when coord odd
    int kyA = (oy & 1) ? 0 : 1;
    int iyA = (oy + 1 - kyA) >> 1;
    int vyB = oy & 1;
    int iyB = (oy >= 1) ? ((oy - 1) >> 1) : 0;
    int kxA = (ox & 1) ? 0 : 1;
    int ixA = (ox + 1 - kxA) >> 1;
    int vxB = ox & 1;
    int ixB = (ox >= 1) ? ((ox - 1) >> 1) : 0;
    int kyT[2] = {kyA, 2}, iyT[2] = {iyA, iyB};
    int kxT[2] = {kxA, 2}, ixT[2] = {ixA, ixB};
    int vy[2] = {1, vyB}, vx[2] = {1, vxB};
    float acc[16];
    #pragma unroll
    for (int j = 0; j < 16; j++) acc[j] = bias[half * 16 + j];
    for (int ic = 0; ic < 64; ic++) {
        const float* xs = in_s + img * 1024 + ic * 16;
        #pragma unroll
        for (int a = 0; a < 2; a++) {
            #pragma unroll
            for (int bb = 0; bb < 2; bb++) {
                float xv = (vy[a] & vx[bb]) ? xs[iyT[a] * 4 + ixT[bb]] : 0.f;
                const float4* wq = (const float4*)w_s + (ic * 9 + kyT[a] * 3 + kxT[bb]) * 8 + half * 4;
                float4 w0 = wq[0], w1 = wq[1], w2 = wq[2], w3 = wq[3];
                acc[0]  += xv * w0.x; acc[1]  += xv * w0.y; acc[2]  += xv * w0.z; acc[3]  += xv * w0.w;
                acc[4]  += xv * w1.x; acc[5]  += xv * w1.y; acc[6]  += xv * w1.z; acc[7]  += xv * w1.w;
                acc[8]  += xv * w2.x; acc[9]  += xv * w2.y; acc[10] += xv * w2.z; acc[11] += xv * w2.w;
                acc[12] += xv * w3.x; acc[13] += xv * w3.y; acc[14] += xv * w3.z; acc[15] += xv * w3.w;
            }
        }
    }
    #pragma unroll
    for (int j = 0; j < 16; j++)
        g_u1[(size_t)((b0 + img) * 32 + half * 16 + j) * 49 + p] = fmaxf(acc[j], 0.f);
}

// ---------------- deconv2: 2 imgs/block, parity (exactly 4 taps via padded 9x9), acc[32] ----------------
// threads 416 (active 392 = 2 img * 196 pix)
__global__ void deconv2_k(const float* __restrict__ w, const float* __restrict__ bias) {
    extern __shared__ float sm[];
    float* in_s = sm;            // 2*32*84 = 5376, padded rows iy+1 in [0,8]
    float* w_s  = sm + 5376;     // 16384, [ic*16+kk][oc]
    int b0 = blockIdx.x * 2, tid = threadIdx.x, nt = blockDim.x;
    float4* z4 = (float4*)in_s;
    for (int i = tid; i < 1344; i += nt) z4[i] = make_float4(0.f, 0.f, 0.f, 0.f);
    for (int i = tid; i < 16384; i += nt) {
        int oc = i & 31, rest = i >> 5;
        w_s[rest * 32 + oc] = w[(rest >> 4) * 512 + oc * 16 + (rest & 15)];
    }
    __syncthreads();
    for (int i = tid; i < 2 * 1568; i += nt) {
        int img = i / 1568, r = i % 1568;
        int ic = r / 49, q = r % 49, y = q / 7, xx = q % 7;
        in_s[(img * 32 + ic) * 84 + (y + 1) * 9 + (xx + 1)] = g_u1[(size_t)(b0 + img) * 1568 + r];
    }
    __syncthreads();
    if (tid >= 392) return;
    int img = tid / 196, p = tid % 196;
    int oy = p / 14, ox = p % 14;
    int c = (oy + 1) & 1;             // ky in {c, c+2}
    int r0 = ((oy + 1 - c) >> 1) + 1; // padded row for ky=c; ky=c+2 -> r0-1
    int d = (ox + 1) & 1;
    int c0 = ((ox + 1 - d) >> 1) + 1;
    float acc[32];
    #pragma unroll
    for (int j = 0; j < 32; j++) acc[j] = bias[j];
    for (int ic = 0; ic < 32; ic++) {
        const float* xs = in_s + (img * 32 + ic) * 84;
        #pragma unroll
        for (int a = 0; a < 2; a++) {
            #pragma unroll
            for (int bb = 0; bb < 2; bb++) {
                float xv = xs[(r0 - a) * 9 + (c0 - bb)];
                int kk = (c + 2 * a) * 4 + (d + 2 * bb);
                const float4* wq = (const float4*)w_s + (ic * 16 + kk) * 8;
                #pragma unroll
                for (int v = 0; v < 8; v++) {
                    float4 wv = wq[v];
                    acc[v * 4]     += xv * wv.x; acc[v * 4 + 1] += xv * wv.y;
                    acc[v * 4 + 2] += xv * wv.z; acc[v * 4 + 3] += xv * wv.w;
                }
            }
        }
    }
    #pragma unroll
    for (int j = 0; j < 32; j++)
        g_u2[(size_t)((b0 + img) * 32 + j) * 196 + p] = fmaxf(acc[j], 0.f);
}

// ---------------- deconv3: 1 img/block, parity 4 taps via padded 16x16, sigmoid ----------------
__global__ void deconv3_k(const float* __restrict__ w, const float* __restrict__ bias,
                          float* __restrict__ out) {
    extern __shared__ float sm[];
    float* in_s = sm;            // 32*256 = 8192, rows iy+1 in [0,15]
    float* w_s  = sm + 8192;     // 512 [ic][kk]
    int b = blockIdx.x, tid = threadIdx.x;
    float4* z4 = (float4*)in_s;
    for (int i = tid; i < 2048; i += 256) z4[i] = make_float4(0.f, 0.f, 0.f, 0.f);
    for (int i = tid; i < 512; i += 256) w_s[i] = w[i];
    __syncthreads();
    for (int i = tid; i < 6272; i += 256) {
        int ic = i / 196, q = i % 196, y = q / 14, xx = q % 14;
        in_s[ic * 256 + (y + 1) * 16 + (xx + 1)] = g_u2[(size_t)b * 6272 + i];
    }
    __syncthreads();
    float b0 = bias[0];
    for (int u = tid; u < 784; u += 256) {
        int oy = u / 28, ox = u % 28;
        int c = (oy + 1) & 1;
        int r0 = ((oy + 1 - c) >> 1) + 1;
        int d = (ox + 1) & 1;
        int c0 = ((ox + 1 - d) >> 1) + 1;
        float acc = b0;
        for (int ic = 0; ic < 32; ic++) {
            const float* xs = in_s + ic * 256;
            const float* wq = w_s + ic * 16;
            #pragma unroll
            for (int a = 0; a < 2; a++)
                #pragma unroll
                for (int bb = 0; bb < 2; bb++)
                    acc += xs[(r0 - a) * 16 + (c0 - bb)] * wq[(c + 2 * a) * 4 + (d + 2 * bb)];
        }
        out[(size_t)b * 784 + u] = 1.0f / (1.0f + expf(-acc));
    }
}

// ---------------- launch ----------------
extern "C" void kernel_launch(void* const* d_in, const int* in_sizes, int n_in,
                              void* d_out, int out_size) {
    const float* x     = (const float*)d_in[0];
    const float* eps   = (const float*)d_in[1];
    const float* w_c1  = (const float*)d_in[2];
    const float* b_c1  = (const float*)d_in[3];
    const float* w_c2  = (const float*)d_in[4];
    const float* b_c2  = (const float*)d_in[5];
    const float* w_c3  = (const float*)d_in[6];
    const float* b_c3  = (const float*)d_in[7];
    const float* w_fc1 = (const float*)d_in[8];
    const float* b_fc1 = (const float*)d_in[9];
    const float* w_mu  = (const float*)d_in[10];
    const float* b_mu  = (const float*)d_in[11];
    const float* w_ls  = (const float*)d_in[12];
    const float* b_ls  = (const float*)d_in[13];
    const float* w_fc2 = (const float*)d_in[14];
    const float* b_fc2 = (const float*)d_in[15];
    const float* w_fc3 = (const float*)d_in[16];
    const float* b_fc3 = (const float*)d_in[17];
    const float* w_d1  = (const float*)d_in[18];
    const float* b_d1  = (const float*)d_in[19];
    const float* w_d2  = (const float*)d_in[20];
    const float* b_d2  = (const float*)d_in[21];
    const float* w_d3  = (const float*)d_in[22];
    const float* b_d3  = (const float*)d_in[23];
    float* out = (float*)d_out;

    cudaFuncSetAttribute(conv2_k,   cudaFuncAttributeMaxDynamicSharedMemorySize, 196608);
    cudaFuncSetAttribute(conv3_k,   cudaFuncAttributeMaxDynamicSharedMemorySize, 202752);
    cudaFuncSetAttribute(deconv1_k, cudaFuncAttributeMaxDynamicSharedMemorySize, 94208);
    cudaFuncSetAttribute(deconv2_k, cudaFuncAttributeMaxDynamicSharedMemorySize, 87040);

    float *p_h3, *p_hf, *p_f2, *p_f3;
    cudaGetSymbolAddress((void**)&p_h3, g_h3);
    cudaGetSymbolAddress((void**)&p_hf, g_hf);
    cudaGetSymbolAddress((void**)&p_f2, g_f2);
    cudaGetSymbolAddress((void**)&p_f3, g_f3);

    conv1_k<<<NB, 256, (784 + 512) * 4>>>(x, w_c1, b_c1);
    conv2_k<<<NB / 4, 416, 196608>>>(w_c2, b_c2);
    conv3_k<<<(NB + 11) / 12, 384, 202752>>>(w_c3, b_c3);
    gemm_k<<<dim3(256 / 64, NB / 64), 256>>>(p_h3, w_fc1, b_fc1, p_hf, NB, 256, 1024, 1);
    latent_k<<<(NB * 20 + 255) / 256, 256>>>(w_mu, b_mu, w_ls, b_ls, eps, out);
    fc2_k<<<(NB * 256 + 255) / 256, 256>>>(w_fc2, b_fc2);
    gemm_k<<<dim3(1024 / 64, NB / 64), 256>>>(p_f2, w_fc3, b_fc3, p_f3, NB, 1024, 256, 1);
    deconv1_k<<<(NB + 4) / 5, 512, 94208>>>(w_d1, b_d1);
    deconv2_k<<<NB / 2, 416, 87040>>>(w_d2, b_d2);
    deconv3_k<<<NB, 256, 34816>>>(w_d3, b_d3, out);
}

// round 4
// speedup vs baseline: 1.4323x; 1.0103x over previous
#include <cuda_runtime.h>
#include <math.h>

#define NB 4096
typedef unsigned long long u64;

// ---- packed f32x2 helpers (Blackwell: fma.rn.f32x2, one issue = 2 fp32 FMA) ----
__device__ __forceinline__ u64 pk2(float lo, float hi) {
    u64 r; asm("mov.b64 %0,{%1,%2};" : "=l"(r) : "f"(lo), "f"(hi)); return r;
}
__device__ __forceinline__ u64 dup2(float x) { return pk2(x, x); }
__device__ __forceinline__ void fm2(u64& d, u64 a, u64 b) {
    asm("fma.rn.f32x2 %0,%1,%2,%0;" : "+l"(d) : "l"(a), "l"(b));
}
__device__ __forceinline__ void up2(u64 v, float& a, float& b) {
    asm("mov.b64 {%0,%1},%2;" : "=f"(a), "=f"(b) : "l"(v));
}

// ---------------- scratch ----------------
__device__ float g_h1[NB * 32 * 196];
__device__ float g_h2[NB * 32 * 49];
__device__ float g_h3[NB * 1024];
__device__ float g_hf[NB * 256];
__device__ float g_z [NB * 20];
__device__ float g_f2[NB * 256];
__device__ float g_f3[NB * 1024];
__device__ float g_u1[NB * 32 * 49];
__device__ float g_u2[NB * 32 * 196];

#define MU_OFF   (NB * 784)
#define LS_OFF   (NB * 784 + NB * 20)

// ---------------- conv1: [B,1,28,28] -> [B,32,14,14], k4 s2 p1, relu ----------------
__global__ void conv1_k(const float* __restrict__ x, const float* __restrict__ w,
                        const float* __restrict__ bias) {
    extern __shared__ float sm[];
    float* in_s = sm;          // 784
    float* w_s  = sm + 784;    // 512, [kk][oc]
    int b = blockIdx.x, tid = threadIdx.x;
    const float* xin = x + b * 784;
    for (int i = tid; i < 784; i += 256) in_s[i] = xin[i];
    for (int i = tid; i < 512; i += 256) { int oc = i & 31, kk = i >> 5; w_s[kk * 32 + oc] = w[oc * 16 + kk]; }
    __syncthreads();
    for (int u = tid; u < 784; u += 256) {
        int p = u >> 2, g = u & 3;
        int oy = p / 14, ox = p % 14;
        u64 acc[4];
        #pragma unroll
        for (int j = 0; j < 4; j++) acc[j] = pk2(bias[g * 8 + 2 * j], bias[g * 8 + 2 * j + 1]);
        #pragma unroll
        for (int ky = 0; ky < 4; ky++) {
            int iy = oy * 2 - 1 + ky;
            if (iy < 0 || iy >= 28) continue;
            #pragma unroll
            for (int kx = 0; kx < 4; kx++) {
                int ix = ox * 2 - 1 + kx;
                if (ix < 0 || ix >= 28) continue;
                u64 xd = dup2(in_s[iy * 28 + ix]);
                const ulonglong2* wq = (const ulonglong2*)(w_s + (ky * 4 + kx) * 32 + g * 8);
                ulonglong2 w0 = wq[0];
                fm2(acc[0], xd, w0.x); fm2(acc[1], xd, w0.y);
                ulonglong2 w1 = wq[1];
                fm2(acc[2], xd, w1.x); fm2(acc[3], xd, w1.y);
            }
        }
        #pragma unroll
        for (int j = 0; j < 4; j++) {
            float lo, hi; up2(acc[j], lo, hi);
            g_h1[(size_t)(b * 32 + g * 8 + 2 * j)     * 196 + p] = fmaxf(lo, 0.f);
            g_h1[(size_t)(b * 32 + g * 8 + 2 * j + 1) * 196 + p] = fmaxf(hi, 0.f);
        }
    }
}

// ---------------- conv2: 4 imgs/block, padded 16x16 inputs, acc 16 oc via 8 f32x2 ----------------
__global__ void conv2_k(const float* __restrict__ w, const float* __restrict__ bias) {
    extern __shared__ float sm[];
    float* in_s = sm;            // 4*32*256 = 32768
    float* w_s  = sm + 32768;    // 16384, [ic*16+kk][oc]
    int b0 = blockIdx.x * 4, tid = threadIdx.x, nt = blockDim.x;
    float4* z4 = (float4*)in_s;
    for (int i = tid; i < 8192; i += nt) z4[i] = make_float4(0.f, 0.f, 0.f, 0.f);
    for (int i = tid; i < 16384; i += nt) {
        int oc = i & 31, rest = i >> 5;
        w_s[rest * 32 + oc] = w[oc * 512 + rest];
    }
    __syncthreads();
    for (int i = tid; i < 4 * 6272; i += nt) {
        int img = i / 6272, r = i % 6272;
        int ic = r / 196, q = r % 196, y = q / 14, xx = q % 14;
        in_s[(img * 32 + ic) * 256 + (y + 1) * 16 + (xx + 1)] = g_h1[(size_t)(b0 + img) * 6272 + r];
    }
    __syncthreads();
    if (tid >= 392) return;
    int img = tid / 98, rr = tid % 98;
    int p = rr % 49, half = rr / 49;
    int oy = p / 7, ox = p % 7;
    u64 acc[8];
    #pragma unroll
    for (int j = 0; j < 8; j++) acc[j] = pk2(bias[half * 16 + 2 * j], bias[half * 16 + 2 * j + 1]);
    for (int ic = 0; ic < 32; ic++) {
        const float* xs = in_s + (img * 32 + ic) * 256 + (oy * 2) * 16 + ox * 2;
        const float* wb = w_s + (ic * 16) * 32 + half * 16;
        #pragma unroll
        for (int kk = 0; kk < 16; kk++) {
            u64 xd = dup2(xs[(kk >> 2) * 16 + (kk & 3)]);
            const ulonglong2* wq = (const ulonglong2*)(wb + kk * 32);
            ulonglong2 w0 = wq[0];
            fm2(acc[0], xd, w0.x); fm2(acc[1], xd, w0.y);
            ulonglong2 w1 = wq[1];
            fm2(acc[2], xd, w1.x); fm2(acc[3], xd, w1.y);
            ulonglong2 w2 = wq[2];
            fm2(acc[4], xd, w2.x); fm2(acc[5], xd, w2.y);
            ulonglong2 w3 = wq[3];
            fm2(acc[6], xd, w3.x); fm2(acc[7], xd, w3.y);
        }
    }
    #pragma unroll
    for (int j = 0; j < 8; j++) {
        float lo, hi; up2(acc[j], lo, hi);
        g_h2[(size_t)((b0 + img) * 32 + half * 16 + 2 * j)     * 49 + p] = fmaxf(lo, 0.f);
        g_h2[(size_t)((b0 + img) * 32 + half * 16 + 2 * j + 1) * 49 + p] = fmaxf(hi, 0.f);
    }
}

// ---------------- conv3: 12 imgs/block, padded 9x9 (ch stride 84), acc 32 oc via 16 f32x2 ----------------
__global__ void conv3_k(const float* __restrict__ w, const float* __restrict__ bias) {
    extern __shared__ float sm[];
    float* in_s = sm;            // 12*32*84 = 32256
    float* w_s  = sm + 32256;    // 18432, [ic*9+kk][oc]
    int b0 = blockIdx.x * 12, tid = threadIdx.x, nt = blockDim.x;
    int nimg = min(12, NB - b0);
    float4* z4 = (float4*)in_s;
    for (int i = tid; i < 8064; i += nt) z4[i] = make_float4(0.f, 0.f, 0.f, 0.f);
    for (int i = tid; i < 18432; i += nt) {
        int oc = i & 63, rest = i >> 6;
        w_s[rest * 64 + oc] = w[oc * 288 + rest];
    }
    __syncthreads();
    for (int i = tid; i < nimg * 1568; i += nt) {
        int img = i / 1568, r = i % 1568;
        int ic = r / 49, q = r % 49, y = q / 7, xx = q % 7;
        in_s[(img * 32 + ic) * 84 + (y + 1) * 9 + (xx + 1)] = g_h2[(size_t)(b0 + img) * 1568 + r];
    }
    __syncthreads();
    int img = tid / 32, rr = tid % 32;
    if (img >= nimg) return;
    int p = rr & 15, half = rr >> 4;
    int oy = p >> 2, ox = p & 3;
    u64 acc[16];
    #pragma unroll
    for (int j = 0; j < 16; j++) acc[j] = pk2(bias[half * 32 + 2 * j], bias[half * 32 + 2 * j + 1]);
    for (int ic = 0; ic < 32; ic++) {
        const float* xs = in_s + (img * 32 + ic) * 84 + (oy * 2) * 9 + ox * 2;
        const float* wb = w_s + (ic * 9) * 64 + half * 32;
        #pragma unroll
        for (int kk = 0; kk < 9; kk++) {
            u64 xd = dup2(xs[(kk / 3) * 9 + (kk % 3)]);
            const ulonglong2* wq = (const ulonglong2*)(wb + kk * 64);
            #pragma unroll
            for (int v = 0; v < 8; v++) {
                ulonglong2 wv = wq[v];
                fm2(acc[2 * v], xd, wv.x); fm2(acc[2 * v + 1], xd, wv.y);
            }
        }
    }
    #pragma unroll
    for (int j = 0; j < 16; j++) {
        float lo, hi; up2(acc[j], lo, hi);
        g_h3[(size_t)((b0 + img) * 64 + half * 32 + 2 * j)     * 16 + p] = fmaxf(lo, 0.f);
        g_h3[(size_t)((b0 + img) * 64 + half * 32 + 2 * j + 1) * 16 + p] = fmaxf(hi, 0.f);
    }
}

// ---------------- NT GEMM with f32x2 ----------------
__global__ void gemm_k(const float* __restrict__ A, const float* __restrict__ W,
                       const float* __restrict__ bias, float* __restrict__ C,
                       int M, int N, int K, int relu) {
    __shared__ float As[16 * 68];
    __shared__ float Ws[16 * 68];
    int tid = threadIdx.x, tx = tid & 15, ty = tid >> 4;
    int m0 = blockIdx.y * 64, n0 = blockIdx.x * 64;
    u64 acc[4][2] = {};
    for (int kt = 0; kt < K; kt += 16) {
        #pragma unroll
        for (int i = 0; i < 4; i++) {
            int idx = tid + i * 256;
            int k = idx & 15, m = idx >> 4;
            As[k * 68 + m] = A[(size_t)(m0 + m) * K + kt + k];
            Ws[k * 68 + m] = W[(size_t)(n0 + m) * K + kt + k];
        }
        __syncthreads();
        #pragma unroll
        for (int kk = 0; kk < 16; kk++) {
            float4 a = *(const float4*)&As[kk * 68 + ty * 4];
            ulonglong2 bv = *(const ulonglong2*)&Ws[kk * 68 + tx * 4];
            u64 a0 = dup2(a.x), a1 = dup2(a.y), a2 = dup2(a.z), a3 = dup2(a.w);
            fm2(acc[0][0], a0, bv.x); fm2(acc[0][1], a0, bv.y);
            fm2(acc[1][0], a1, bv.x); fm2(acc[1][1], a1, bv.y);
            fm2(acc[2][0], a2, bv.x); fm2(acc[2][1], a2, bv.y);
            fm2(acc[3][0], a3, bv.x); fm2(acc[3][1], a3, bv.y);
        }
        __syncthreads();
    }
    #pragma unroll
    for (int i = 0; i < 4; i++) {
        int m = m0 + ty * 4 + i;
        #pragma unroll
        for (int jp = 0; jp < 2; jp++) {
            float lo, hi; up2(acc[i][jp], lo, hi);
            int n = n0 + tx * 4 + 2 * jp;
            float v0 = lo + bias[n], v1 = hi + bias[n + 1];
            if (relu) { v0 = fmaxf(v0, 0.f); v1 = fmaxf(v1, 0.f); }
            C[(size_t)m * N + n] = v0;
            C[(size_t)m * N + n + 1] = v1;
        }
    }
}

// ---------------- latent ----------------
__global__ void latent_k(const float* __restrict__ w_mu, const float* __restrict__ b_mu,
                         const float* __restrict__ w_ls, const float* __restrict__ b_ls,
                         const float* __restrict__ eps, float* __restrict__ out) {
    int idx = blockIdx.x * 256 + threadIdx.x;
    if (idx >= NB * 20) return;
    int b = idx / 20, l = idx % 20;
    const float4* h4 = (const float4*)(g_hf + (size_t)b * 256);
    const float4* wm = (const float4*)(w_mu + (size_t)l * 256);
    const float4* wl = (const float4*)(w_ls + (size_t)l * 256);
    float sm_ = 0.f, sl_ = 0.f;
    #pragma unroll 8
    for (int k = 0; k < 64; k++) {
        float4 h = h4[k], a = wm[k], c = wl[k];
        sm_ += h.x * a.x + h.y * a.y + h.z * a.z + h.w * a.w;
        sl_ += h.x * c.x + h.y * c.y + h.z * c.z + h.w * c.w;
    }
    float mu = sm_ + b_mu[l];
    float ls = sl_ + b_ls[l];
    out[MU_OFF + idx] = mu;
    out[LS_OFF + idx] = ls;
    float m = mu, s = ls;
    #pragma unroll 4
    for (int i = 0; i < 100; i++) {
        m = m + 0.1f * m;
        s = s + 0.05f * (expf(s) - 1.0f);
    }
    g_z[idx] = eps[idx] * expf(0.5f * s) + m;
}

// ---------------- fc2 ----------------
__global__ void fc2_k(const float* __restrict__ w, const float* __restrict__ bias) {
    int idx = blockIdx.x * 256 + threadIdx.x;
    if (idx >= NB * 256) return;
    int b = idx >> 8, o = idx & 255;
    const float* z = g_z + (size_t)b * 20;
    const float* wr = w + (size_t)o * 20;
    float acc = bias[o];
    #pragma unroll
    for (int k = 0; k < 20; k++) acc += z[k] * wr[k];
    g_f2[idx] = fmaxf(acc, 0.f);
}

// ---------------- deconv1: 5 imgs/block, predicated 2x2 taps, 16 oc via 8 f32x2 ----------------
__global__ void deconv1_k(const float* __restrict__ w, const float* __restrict__ bias) {
    extern __shared__ float sm[];
    float* in_s = sm;            // 5*1024
    float* w_s  = sm + 5120;     // 18432, [ic*9+kk][oc]
    int b0 = blockIdx.x * 5, tid = threadIdx.x, nt = blockDim.x;
    int nimg = min(5, NB - b0);
    for (int i = tid; i < nimg * 1024; i += nt) in_s[i] = g_f3[(size_t)b0 * 1024 + i];
    for (int i = tid; i < 18432; i += nt) {
        int oc = i & 31, rest = i >> 5;
        int ic = rest / 9, kk = rest % 9;
        w_s[rest * 32 + oc] = w[ic * 288 + oc * 9 + kk];
    }
    __syncthreads();
    if (tid >= 490) return;
    int img = tid / 98, rr = tid % 98;
    if (img >= nimg) return;
    int p = rr % 49, half = rr / 49;
    int oy = p / 7, ox = p % 7;
    int kyA = (oy & 1) ? 0 : 1;
    int iyA = (oy + 1 - kyA) >> 1;
    int vyB = oy & 1;
    int iyB = (oy >= 1) ? ((oy - 1) >> 1) : 0;
    int kxA = (ox & 1) ? 0 : 1;
    int ixA = (ox + 1 - kxA) >> 1;
    int vxB = ox & 1;
    int ixB = (ox >= 1) ? ((ox - 1) >> 1) : 0;
    int kyT[2] = {kyA, 2}, iyT[2] = {iyA, iyB};
    int kxT[2] = {kxA, 2}, ixT[2] = {ixA, ixB};
    int vy[2] = {1, vyB}, vx[2] = {1, vxB};
    u64 acc[8];
    #pragma unroll
    for (int j = 0; j < 8; j++) acc[j] = pk2(bias[half * 16 + 2 * j], bias[half * 16 + 2 * j + 1]);
    for (int ic = 0; ic < 64; ic++) {
        const float* xs = in_s + img * 1024 + ic * 16;
        #pragma unroll
        for (int a = 0; a < 2; a++) {
            #pragma unroll
            for (int bb = 0; bb < 2; bb++) {
                float xv = (vy[a] & vx[bb]) ? xs[iyT[a] * 4 + ixT[bb]] : 0.f;
                u64 xd = dup2(xv);
                const ulonglong2* wq = (const ulonglong2*)(w_s + (ic * 9 + kyT[a] * 3 + kxT[bb]) * 32 + half * 16);
                ulonglong2 w0 = wq[0];
                fm2(acc[0], xd, w0.x); fm2(acc[1], xd, w0.y);
                ulonglong2 w1 = wq[1];
                fm2(acc[2], xd, w1.x); fm2(acc[3], xd, w1.y);
                ulonglong2 w2 = wq[2];
                fm2(acc[4], xd, w2.x); fm2(acc[5], xd, w2.y);
                ulonglong2 w3 = wq[3];
                fm2(acc[6], xd, w3.x); fm2(acc[7], xd, w3.y);
            }
        }
    }
    #pragma unroll
    for (int j = 0; j < 8; j++) {
        float lo, hi; up2(acc[j], lo, hi);
        g_u1[(size_t)((b0 + img) * 32 + half * 16 + 2 * j)     * 49 + p] = fmaxf(lo, 0.f);
        g_u1[(size_t)((b0 + img) * 32 + half * 16 + 2 * j + 1) * 49 + p] = fmaxf(hi, 0.f);
    }
}

// ---------------- deconv2: 2 imgs/block, exact 4 taps, 32 oc via 16 f32x2 ----------------
__global__ void deconv2_k(const float* __restrict__ w, const float* __restrict__ bias) {
    extern __shared__ float sm[];
    float* in_s = sm;            // 2*32*84 = 5376
    float* w_s  = sm + 5376;     // 16384, [ic*16+kk][oc]
    int b0 = blockIdx.x * 2, tid = threadIdx.x, nt = blockDim.x;
    float4* z4 = (float4*)in_s;
    for (int i = tid; i < 1344; i += nt) z4[i] = make_float4(0.f, 0.f, 0.f, 0.f);
    for (int i = tid; i < 16384; i += nt) {
        int oc = i & 31, rest = i >> 5;
        w_s[rest * 32 + oc] = w[(rest >> 4) * 512 + oc * 16 + (rest & 15)];
    }
    __syncthreads();
    for (int i = tid; i < 2 * 1568; i += nt) {
        int img = i / 1568, r = i % 1568;
        int ic = r / 49, q = r % 49, y = q / 7, xx = q % 7;
        in_s[(img * 32 + ic) * 84 + (y + 1) * 9 + (xx + 1)] = g_u1[(size_t)(b0 + img) * 1568 + r];
    }
    __syncthreads();
    if (tid >= 392) return;
    int img = tid / 196, p = tid % 196;
    int oy = p / 14, ox = p % 14;
    int c = (oy + 1) & 1;
    int r0 = ((oy + 1 - c) >> 1) + 1;
    int d = (ox + 1) & 1;
    int c0 = ((ox + 1 - d) >> 1) + 1;
    u64 acc[16];
    #pragma unroll
    for (int j = 0; j < 16; j++) acc[j] = pk2(bias[2 * j], bias[2 * j + 1]);
    for (int ic = 0; ic < 32; ic++) {
        const float* xs = in_s + (img * 32 + ic) * 84;
        #pragma unroll
        for (int a = 0; a < 2; a++) {
            #pragma unroll
            for (int bb = 0; bb < 2; bb++) {
                u64 xd = dup2(xs[(r0 - a) * 9 + (c0 - bb)]);
                int kk = (c + 2 * a) * 4 + (d + 2 * bb);
                const ulonglong2* wq = (const ulonglong2*)(w_s + (ic * 16 + kk) * 32);
                #pragma unroll
                for (int v = 0; v < 8; v++) {
                    ulonglong2 wv = wq[v];
                    fm2(acc[2 * v], xd, wv.x); fm2(acc[2 * v + 1], xd, wv.y);
                }
            }
        }
    }
    #pragma unroll
    for (int j = 0; j < 16; j++) {
        float lo, hi; up2(acc[j], lo, hi);
        g_u2[(size_t)((b0 + img) * 32 + 2 * j)     * 196 + p] = fmaxf(lo, 0.f);
        g_u2[(size_t)((b0 + img) * 32 + 2 * j + 1) * 196 + p] = fmaxf(hi, 0.f);
    }
}

// ---------------- deconv3: 2 imgs/block, thread = 1x4 output run, parity-packed weights ----------------
__global__ void deconv3_k(const float* __restrict__ w, const float* __restrict__ bias,
                          float* __restrict__ out) {
    extern __shared__ float sm[];
    float* in_s = sm;                    // 2*32*256 = 16384 floats (padded 16x16)
    u64*   wpk  = (u64*)(sm + 16384);    // 256 u64: [(ky*32+ic)*2 + t]
    int b0 = blockIdx.x * 2, tid = threadIdx.x, nt = blockDim.x;
    float4* z4 = (float4*)in_s;
    for (int i = tid; i < 4096; i += nt) z4[i] = make_float4(0.f, 0.f, 0.f, 0.f);
    for (int i = tid; i < 256; i += nt) {
        int t = i & 1, rest = i >> 1;
        int ic = rest & 31, ky = rest >> 5;
        wpk[(ky * 32 + ic) * 2 + t] = pk2(w[ic * 16 + ky * 4 + 2 * t + 1], w[ic * 16 + ky * 4 + 2 * t]);
    }
    __syncthreads();
    for (int i = tid; i < 2 * 6272; i += nt) {
        int img = i / 6272, r = i % 6272;
        int ic = r / 196, q = r % 196, y = q / 14, xx = q % 14;
        in_s[(img * 32 + ic) * 256 + (y + 1) * 16 + (xx + 1)] = g_u2[(size_t)(b0 + img) * 6272 + r];
    }
    __syncthreads();
    if (tid >= 392) return;
    int img = tid / 196, q = tid % 196;
    int oy = q / 7, t = q % 7;
    int mm = 2 * t;
    int c = (oy + 1) & 1;
    int r0 = ((oy + 1 - c) >> 1) + 1;
    float b0v = bias[0];
    u64 p1 = pk2(b0v, b0v), p2 = pk2(0.f, 0.f);
    for (int ic = 0; ic < 32; ic++) {
        const float* xs = in_s + (img * 32 + ic) * 256;
        const float* row0 = xs + r0 * 16 + mm;
        const float* row1 = row0 - 16;
        float i00 = row0[0], i01 = row0[1], i02 = row0[2], i03 = row0[3];
        float i10 = row1[0], i11 = row1[1], i12 = row1[2], i13 = row1[3];
        u64 q01a = pk2(i00, i01), q12a = pk2(i01, i02), q23a = pk2(i02, i03);
        u64 q01b = pk2(i10, i11), q12b = pk2(i11, i12), q23b = pk2(i12, i13);
        ulonglong2 wa = *(const ulonglong2*)&wpk[(c * 32 + ic) * 2];
        ulonglong2 wb = *(const ulonglong2*)&wpk[((c + 2) * 32 + ic) * 2];
        fm2(p1, q12a, wa.x); fm2(p1, q01a, wa.y);
        fm2(p2, q23a, wa.x); fm2(p2, q12a, wa.y);
        fm2(p1, q12b, wb.x); fm2(p1, q01b, wb.y);
        fm2(p2, q23b, wb.x); fm2(p2, q12b, wb.y);
    }
    float v0, v1, v2, v3;
    up2(p1, v0, v1); up2(p2, v2, v3);
    v2 += b0v; v3 += b0v;
    size_t ob = (size_t)(b0 + img) * 784 + oy * 28 + 4 * t;
    out[ob]     = 1.0f / (1.0f + expf(-v0));
    out[ob + 1] = 1.0f / (1.0f + expf(-v1));
    out[ob + 2] = 1.0f / (1.0f + expf(-v2));
    out[ob + 3] = 1.0f / (1.0f + expf(-v3));
}

// ---------------- launch ----------------
extern "C" void kernel_launch(void* const* d_in, const int* in_sizes, int n_in,
                              void* d_out, int out_size) {
    const float* x     = (const float*)d_in[0];
    const float* eps   = (const float*)d_in[1];
    const float* w_c1  = (const float*)d_in[2];
    const float* b_c1  = (const float*)d_in[3];
    const float* w_c2  = (const float*)d_in[4];
    const float* b_c2  = (const float*)d_in[5];
    const float* w_c3  = (const float*)d_in[6];
    const float* b_c3  = (const float*)d_in[7];
    const float* w_fc1 = (const float*)d_in[8];
    const float* b_fc1 = (const float*)d_in[9];
    const float* w_mu  = (const float*)d_in[10];
    const float* b_mu  = (const float*)d_in[11];
    const float* w_ls  = (const float*)d_in[12];
    const float* b_ls  = (const float*)d_in[13];
    const float* w_fc2 = (const float*)d_in[14];
    const float* b_fc2 = (const float*)d_in[15];
    const float* w_fc3 = (const float*)d_in[16];
    const float* b_fc3 = (const float*)d_in[17];
    const float* w_d1  = (const float*)d_in[18];
    const float* b_d1  = (const float*)d_in[19];
    const float* w_d2  = (const float*)d_in[20];
    const float* b_d2  = (const float*)d_in[21];
    const float* w_d3  = (const float*)d_in[22];
    const float* b_d3  = (const float*)d_in[23];
    float* out = (float*)d_out;

    cudaFuncSetAttribute(conv2_k,   cudaFuncAttributeMaxDynamicSharedMemorySize, 196608);
    cudaFuncSetAttribute(conv3_k,   cudaFuncAttributeMaxDynamicSharedMemorySize, 202752);
    cudaFuncSetAttribute(deconv1_k, cudaFuncAttributeMaxDynamicSharedMemorySize, 94208);
    cudaFuncSetAttribute(deconv2_k, cudaFuncAttributeMaxDynamicSharedMemorySize, 87040);
    cudaFuncSetAttribute(deconv3_k, cudaFuncAttributeMaxDynamicSharedMemorySize, 69632);

    float *p_h3, *p_hf, *p_f2, *p_f3;
    cudaGetSymbolAddress((void**)&p_h3, g_h3);
    cudaGetSymbolAddress((void**)&p_hf, g_hf);
    cudaGetSymbolAddress((void**)&p_f2, g_f2);
    cudaGetSymbolAddress((void**)&p_f3, g_f3);

    conv1_k<<<NB, 256, (784 + 512) * 4>>>(x, w_c1, b_c1);
    conv2_k<<<NB / 4, 416, 196608>>>(w_c2, b_c2);
    conv3_k<<<(NB + 11) / 12, 384, 202752>>>(w_c3, b_c3);
    gemm_k<<<dim3(256 / 64, NB / 64), 256>>>(p_h3, w_fc1, b_fc1, p_hf, NB, 256, 1024, 1);
    latent_k<<<(NB * 20 + 255) / 256, 256>>>(w_mu, b_mu, w_ls, b_ls, eps, out);
    fc2_k<<<(NB * 256 + 255) / 256, 256>>>(w_fc2, b_fc2);
    gemm_k<<<dim3(1024 / 64, NB / 64), 256>>>(p_f2, w_fc3, b_fc3, p_f3, NB, 1024, 256, 1);
    deconv1_k<<<(NB + 4) / 5, 512, 94208>>>(w_d1, b_d1);
    deconv2_k<<<NB / 2, 416, 87040>>>(w_d2, b_d2);
    deconv3_k<<<NB / 2, 416, 69632>>>(w_d3, b_d3, out);
}

// round 5
// speedup vs baseline: 2.1531x; 1.5033x over previous
#include <cuda_runtime.h>
#include <math.h>

#define NB 4096
typedef unsigned long long u64;

__device__ __forceinline__ u64 pk2(float lo, float hi) {
    u64 r; asm("mov.b64 %0,{%1,%2};" : "=l"(r) : "f"(lo), "f"(hi)); return r;
}
__device__ __forceinline__ u64 dup2(float x) { return pk2(x, x); }
__device__ __forceinline__ void fm2(u64& d, u64 a, u64 b) {
    asm("fma.rn.f32x2 %0,%1,%2,%0;" : "+l"(d) : "l"(a), "l"(b));
}
__device__ __forceinline__ void up2(u64 v, float& a, float& b) {
    asm("mov.b64 {%0,%1},%2;" : "=f"(a), "=f"(b) : "l"(v));
}

// ---------------- scratch ----------------
__device__ float g_h1[NB * 32 * 196];
__device__ float g_h2[NB * 32 * 49];
__device__ float g_h3[NB * 1024];
__device__ float g_hf[NB * 256];
__device__ float g_z [NB * 20];
__device__ float g_f2[NB * 256];
__device__ float g_f3[NB * 1024];
__device__ float g_u1[NB * 32 * 49];
__device__ float g_u2[NB * 32 * 196];

#define MU_OFF   (NB * 784)
#define LS_OFF   (NB * 784 + NB * 20)

// ---------------- conv1: [B,1,28,28] -> [B,32,14,14], k4 s2 p1, relu ----------------
__global__ void conv1_k(const float* __restrict__ x, const float* __restrict__ w,
                        const float* __restrict__ bias) {
    extern __shared__ float sm[];
    float* in_s = sm;          // 784
    float* w_s  = sm + 784;    // 512, [kk][oc]
    int b = blockIdx.x, tid = threadIdx.x;
    const float* xin = x + b * 784;
    for (int i = tid; i < 784; i += 256) in_s[i] = xin[i];
    for (int i = tid; i < 512; i += 256) { int oc = i & 31, kk = i >> 5; w_s[kk * 32 + oc] = w[oc * 16 + kk]; }
    __syncthreads();
    for (int u = tid; u < 784; u += 256) {
        int p = u >> 2, g = u & 3;
        int oy = p / 14, ox = p % 14;
        u64 acc[4];
        #pragma unroll
        for (int j = 0; j < 4; j++) acc[j] = pk2(bias[g * 8 + 2 * j], bias[g * 8 + 2 * j + 1]);
        #pragma unroll
        for (int ky = 0; ky < 4; ky++) {
            int iy = oy * 2 - 1 + ky;
            if (iy < 0 || iy >= 28) continue;
            #pragma unroll
            for (int kx = 0; kx < 4; kx++) {
                int ix = ox * 2 - 1 + kx;
                if (ix < 0 || ix >= 28) continue;
                u64 xd = dup2(in_s[iy * 28 + ix]);
                const ulonglong2* wq = (const ulonglong2*)(w_s + (ky * 4 + kx) * 32 + g * 8);
                ulonglong2 w0 = wq[0];
                fm2(acc[0], xd, w0.x); fm2(acc[1], xd, w0.y);
                ulonglong2 w1 = wq[1];
                fm2(acc[2], xd, w1.x); fm2(acc[3], xd, w1.y);
            }
        }
        #pragma unroll
        for (int j = 0; j < 4; j++) {
            float lo, hi; up2(acc[j], lo, hi);
            g_h1[(size_t)(b * 32 + g * 8 + 2 * j)     * 196 + p] = fmaxf(lo, 0.f);
            g_h1[(size_t)(b * 32 + g * 8 + 2 * j + 1) * 196 + p] = fmaxf(hi, 0.f);
        }
    }
}

// ---------------- conv2: 4 imgs/block; input pitch 18/288 (bank-safe); weight pitch 36 ----------------
__global__ void conv2_k(const float* __restrict__ w, const float* __restrict__ bias) {
    extern __shared__ float sm[];
    float* in_s = sm;            // 4*32*288 = 36864
    float* w_s  = sm + 36864;    // 512 rows * 36 pitch = 18432, [ic*16+kk][oc]
    int b0 = blockIdx.x * 4, tid = threadIdx.x, nt = blockDim.x;
    float4* z4 = (float4*)in_s;
    for (int i = tid; i < 9216; i += nt) z4[i] = make_float4(0.f, 0.f, 0.f, 0.f);
    for (int i = tid; i < 16384; i += nt) {
        int oc = i & 31, rest = i >> 5;
        w_s[rest * 36 + oc] = w[oc * 512 + rest];
    }
    __syncthreads();
    for (int i = tid; i < 4 * 6272; i += nt) {
        int img = i / 6272, r = i % 6272;
        int ic = r / 196, q = r % 196, y = q / 14, xx = q % 14;
        in_s[(img * 32 + ic) * 288 + (y + 1) * 18 + (xx + 1)] = g_h1[(size_t)(b0 + img) * 6272 + r];
    }
    __syncthreads();
    if (tid >= 392) return;
    int img = tid / 98, rr = tid % 98;
    int p = rr % 49, half = rr / 49;
    int oy = p / 7, ox = p % 7;
    u64 acc[8];
    #pragma unroll
    for (int j = 0; j < 8; j++) acc[j] = pk2(bias[half * 16 + 2 * j], bias[half * 16 + 2 * j + 1]);
    for (int ic = 0; ic < 32; ic++) {
        const float* xs = in_s + (img * 32 + ic) * 288 + (oy * 2) * 18 + ox * 2;
        const float* wb = w_s + (ic * 16) * 36 + half * 16;
        #pragma unroll
        for (int kk = 0; kk < 16; kk++) {
            u64 xd = dup2(xs[(kk >> 2) * 18 + (kk & 3)]);
            const ulonglong2* wq = (const ulonglong2*)(wb + kk * 36);
            ulonglong2 w0 = wq[0];
            fm2(acc[0], xd, w0.x); fm2(acc[1], xd, w0.y);
            ulonglong2 w1 = wq[1];
            fm2(acc[2], xd, w1.x); fm2(acc[3], xd, w1.y);
            ulonglong2 w2 = wq[2];
            fm2(acc[4], xd, w2.x); fm2(acc[5], xd, w2.y);
            ulonglong2 w3 = wq[3];
            fm2(acc[6], xd, w3.x); fm2(acc[7], xd, w3.y);
        }
    }
    #pragma unroll
    for (int j = 0; j < 8; j++) {
        float lo, hi; up2(acc[j], lo, hi);
        g_h2[(size_t)((b0 + img) * 32 + half * 16 + 2 * j)     * 49 + p] = fmaxf(lo, 0.f);
        g_h2[(size_t)((b0 + img) * 32 + half * 16 + 2 * j + 1) * 49 + p] = fmaxf(hi, 0.f);
    }
}

// ---------------- conv3: 12 imgs/block; weight pitch 68 ----------------
__global__ void conv3_k(const float* __restrict__ w, const float* __restrict__ bias) {
    extern __shared__ float sm[];
    float* in_s = sm;            // 12*32*84 = 32256
    float* w_s  = sm + 32256;    // 288 rows * 68 = 19584, [ic*9+kk][oc]
    int b0 = blockIdx.x * 12, tid = threadIdx.x, nt = blockDim.x;
    int nimg = min(12, NB - b0);
    float4* z4 = (float4*)in_s;
    for (int i = tid; i < 8064; i += nt) z4[i] = make_float4(0.f, 0.f, 0.f, 0.f);
    for (int i = tid; i < 18432; i += nt) {
        int oc = i & 63, rest = i >> 6;
        w_s[rest * 68 + oc] = w[oc * 288 + rest];
    }
    __syncthreads();
    for (int i = tid; i < nimg * 1568; i += nt) {
        int img = i / 1568, r = i % 1568;
        int ic = r / 49, q = r % 49, y = q / 7, xx = q % 7;
        in_s[(img * 32 + ic) * 84 + (y + 1) * 9 + (xx + 1)] = g_h2[(size_t)(b0 + img) * 1568 + r];
    }
    __syncthreads();
    int img = tid / 32, rr = tid % 32;
    if (img >= nimg) return;
    int p = rr & 15, half = rr >> 4;
    int oy = p >> 2, ox = p & 3;
    u64 acc[16];
    #pragma unroll
    for (int j = 0; j < 16; j++) acc[j] = pk2(bias[half * 32 + 2 * j], bias[half * 32 + 2 * j + 1]);
    for (int ic = 0; ic < 32; ic++) {
        const float* xs = in_s + (img * 32 + ic) * 84 + (oy * 2) * 9 + ox * 2;
        const float* wb = w_s + (ic * 9) * 68 + half * 32;
        #pragma unroll
        for (int kk = 0; kk < 9; kk++) {
            u64 xd = dup2(xs[(kk / 3) * 9 + (kk % 3)]);
            const ulonglong2* wq = (const ulonglong2*)(wb + kk * 68);
            #pragma unroll
            for (int v = 0; v < 8; v++) {
                ulonglong2 wv = wq[v];
                fm2(acc[2 * v], xd, wv.x); fm2(acc[2 * v + 1], xd, wv.y);
            }
        }
    }
    #pragma unroll
    for (int j = 0; j < 16; j++) {
        float lo, hi; up2(acc[j], lo, hi);
        g_h3[(size_t)((b0 + img) * 64 + half * 32 + 2 * j)     * 16 + p] = fmaxf(lo, 0.f);
        g_h3[(size_t)((b0 + img) * 64 + half * 32 + 2 * j + 1) * 16 + p] = fmaxf(hi, 0.f);
    }
}

// ---------------- NT GEMM: BM=32, BN=64, BK=16, 128 threads (more blocks -> fill chip) ----------------
__global__ void gemm_k(const float* __restrict__ A, const float* __restrict__ W,
                       const float* __restrict__ bias, float* __restrict__ C,
                       int M, int N, int K, int relu) {
    __shared__ float As[16 * 36];
    __shared__ float Ws[16 * 68];
    int tid = threadIdx.x, tx = tid & 15, ty = tid >> 4;   // ty 0..7
    int m0 = blockIdx.y * 32, n0 = blockIdx.x * 64;
    u64 acc[4][2] = {};
    for (int kt = 0; kt < K; kt += 16) {
        #pragma unroll
        for (int i = 0; i < 4; i++) {
            int idx = tid + i * 128;
            int k = idx & 15, m = idx >> 4;           // m 0..31
            As[k * 36 + m] = A[(size_t)(m0 + m) * K + kt + k];
        }
        #pragma unroll
        for (int i = 0; i < 8; i++) {
            int idx = tid + i * 128;
            int k = idx & 15, n = idx >> 4;           // n 0..63
            Ws[k * 68 + n] = W[(size_t)(n0 + n) * K + kt + k];
        }
        __syncthreads();
        #pragma unroll
        for (int kk = 0; kk < 16; kk++) {
            float4 a = *(const float4*)&As[kk * 36 + ty * 4];
            ulonglong2 bv = *(const ulonglong2*)&Ws[kk * 68 + tx * 4];
            u64 a0 = dup2(a.x), a1 = dup2(a.y), a2 = dup2(a.z), a3 = dup2(a.w);
            fm2(acc[0][0], a0, bv.x); fm2(acc[0][1], a0, bv.y);
            fm2(acc[1][0], a1, bv.x); fm2(acc[1][1], a1, bv.y);
            fm2(acc[2][0], a2, bv.x); fm2(acc[2][1], a2, bv.y);
            fm2(acc[3][0], a3, bv.x); fm2(acc[3][1], a3, bv.y);
        }
        __syncthreads();
    }
    #pragma unroll
    for (int i = 0; i < 4; i++) {
        int m = m0 + ty * 4 + i;
        #pragma unroll
        for (int jp = 0; jp < 2; jp++) {
            float lo, hi; up2(acc[i][jp], lo, hi);
            int n = n0 + tx * 4 + 2 * jp;
            float v0 = lo + bias[n], v1 = hi + bias[n + 1];
            if (relu) { v0 = fmaxf(v0, 0.f); v1 = fmaxf(v1, 0.f); }
            C[(size_t)m * N + n] = v0;
            C[(size_t)m * N + n + 1] = v1;
        }
    }
}

// ---------------- latent ----------------
__global__ void latent_k(const float* __restrict__ w_mu, const float* __restrict__ b_mu,
                         const float* __restrict__ w_ls, const float* __restrict__ b_ls,
                         const float* __restrict__ eps, float* __restrict__ out) {
    int idx = blockIdx.x * 256 + threadIdx.x;
    if (idx >= NB * 20) return;
    int b = idx / 20, l = idx % 20;
    const float4* h4 = (const float4*)(g_hf + (size_t)b * 256);
    const float4* wm = (const float4*)(w_mu + (size_t)l * 256);
    const float4* wl = (const float4*)(w_ls + (size_t)l * 256);
    float sm_ = 0.f, sl_ = 0.f;
    #pragma unroll 8
    for (int k = 0; k < 64; k++) {
        float4 h = h4[k], a = wm[k], c = wl[k];
        sm_ += h.x * a.x + h.y * a.y + h.z * a.z + h.w * a.w;
        sl_ += h.x * c.x + h.y * c.y + h.z * c.z + h.w * c.w;
    }
    float mu = sm_ + b_mu[l];
    float ls = sl_ + b_ls[l];
    out[MU_OFF + idx] = mu;
    out[LS_OFF + idx] = ls;
    float m = mu, s = ls;
    #pragma unroll 4
    for (int i = 0; i < 100; i++) {
        m = m + 0.1f * m;
        s = s + 0.05f * (expf(s) - 1.0f);
    }
    g_z[idx] = eps[idx] * expf(0.5f * s) + m;
}

// ---------------- fc2 ----------------
__global__ void fc2_k(const float* __restrict__ w, const float* __restrict__ bias) {
    int idx = blockIdx.x * 256 + threadIdx.x;
    if (idx >= NB * 256) return;
    int b = idx >> 8, o = idx & 255;
    const float* z = g_z + (size_t)b * 20;
    const float* wr = w + (size_t)o * 20;
    float acc = bias[o];
    #pragma unroll
    for (int k = 0; k < 20; k++) acc += z[k] * wr[k];
    g_f2[idx] = fmaxf(acc, 0.f);
}

// ---------------- deconv1: 5 imgs/block; weight pitch 36 ----------------
__global__ void deconv1_k(const float* __restrict__ w, const float* __restrict__ bias) {
    extern __shared__ float sm[];
    float* in_s = sm;            // 5*1024
    float* w_s  = sm + 5120;     // 576 rows * 36 = 20736, [ic*9+kk][oc]
    int b0 = blockIdx.x * 5, tid = threadIdx.x, nt = blockDim.x;
    int nimg = min(5, NB - b0);
    for (int i = tid; i < nimg * 1024; i += nt) in_s[i] = g_f3[(size_t)b0 * 1024 + i];
    for (int i = tid; i < 18432; i += nt) {
        int oc = i & 31, rest = i >> 5;
        int ic = rest / 9, kk = rest % 9;
        w_s[rest * 36 + oc] = w[ic * 288 + oc * 9 + kk];
    }
    __syncthreads();
    if (tid >= 490) return;
    int img = tid / 98, rr = tid % 98;
    if (img >= nimg) return;
    int p = rr % 49, half = rr / 49;
    int oy = p / 7, ox = p % 7;
    int kyA = (oy & 1) ? 0 : 1;
    int iyA = (oy + 1 - kyA) >> 1;
    int vyB = oy & 1;
    int iyB = (oy >= 1) ? ((oy - 1) >> 1) : 0;
    int kxA = (ox & 1) ? 0 : 1;
    int ixA = (ox + 1 - kxA) >> 1;
    int vxB = ox & 1;
    int ixB = (ox >= 1) ? ((ox - 1) >> 1) : 0;
    int kyT[2] = {kyA, 2}, iyT[2] = {iyA, iyB};
    int kxT[2] = {kxA, 2}, ixT[2] = {ixA, ixB};
    int vy[2] = {1, vyB}, vx[2] = {1, vxB};
    u64 acc[8];
    #pragma unroll
    for (int j = 0; j < 8; j++) acc[j] = pk2(bias[half * 16 + 2 * j], bias[half * 16 + 2 * j + 1]);
    for (int ic = 0; ic < 64; ic++) {
        const float* xs = in_s + img * 1024 + ic * 16;
        #pragma unroll
        for (int a = 0; a < 2; a++) {
            #pragma unroll
            for (int bb = 0; bb < 2; bb++) {
                float xv = (vy[a] & vx[bb]) ? xs[iyT[a] * 4 + ixT[bb]] : 0.f;
                u64 xd = dup2(xv);
                const ulonglong2* wq = (const ulonglong2*)(w_s + (ic * 9 + kyT[a] * 3 + kxT[bb]) * 36 + half * 16);
                ulonglong2 w0 = wq[0];
                fm2(acc[0], xd, w0.x); fm2(acc[1], xd, w0.y);
                ulonglong2 w1 = wq[1];
                fm2(acc[2], xd, w1.x); fm2(acc[3], xd, w1.y);
                ulonglong2 w2 = wq[2];
                fm2(acc[4], xd, w2.x); fm2(acc[5], xd, w2.y);
                ulonglong2 w3 = wq[3];
                fm2(acc[6], xd, w3.x); fm2(acc[7], xd, w3.y);
            }
        }
    }
    #pragma unroll
    for (int j = 0; j < 8; j++) {
        float lo, hi; up2(acc[j], lo, hi);
        g_u1[(size_t)((b0 + img) * 32 + half * 16 + 2 * j)     * 49 + p] = fmaxf(lo, 0.f);
        g_u1[(size_t)((b0 + img) * 32 + half * 16 + 2 * j + 1) * 49 + p] = fmaxf(hi, 0.f);
    }
}

// ---------------- deconv2: 2 imgs/block; weight pitch 36 (kills 4-way kk conflict) ----------------
__global__ void deconv2_k(const float* __restrict__ w, const float* __restrict__ bias) {
    extern __shared__ float sm[];
    float* in_s = sm;            // 2*32*84 = 5376
    float* w_s  = sm + 5376;     // 512 rows * 36 = 18432, [ic*16+kk][oc]
    int b0 = blockIdx.x * 2, tid = threadIdx.x, nt = blockDim.x;
    float4* z4 = (float4*)in_s;
    for (int i = tid; i < 1344; i += nt) z4[i] = make_float4(0.f, 0.f, 0.f, 0.f);
    for (int i = tid; i < 16384; i += nt) {
        int oc = i & 31, rest = i >> 5;
        w_s[rest * 36 + oc] = w[(rest >> 4) * 512 + oc * 16 + (rest & 15)];
    }
    __syncthreads();
    for (int i = tid; i < 2 * 1568; i += nt) {
        int img = i / 1568, r = i % 1568;
        int ic = r / 49, q = r % 49, y = q / 7, xx = q % 7;
        in_s[(img * 32 + ic) * 84 + (y + 1) * 9 + (xx + 1)] = g_u1[(size_t)(b0 + img) * 1568 + r];
    }
    __syncthreads();
    if (tid >= 392) return;
    int img = tid / 196, p = tid % 196;
    int oy = p / 14, ox = p % 14;
    int c = (oy + 1) & 1;
    int r0 = ((oy + 1 - c) >> 1) + 1;
    int d = (ox + 1) & 1;
    int c0 = ((ox + 1 - d) >> 1) + 1;
    u64 acc[16];
    #pragma unroll
    for (int j = 0; j < 16; j++) acc[j] = pk2(bias[2 * j], bias[2 * j + 1]);
    for (int ic = 0; ic < 32; ic++) {
        const float* xs = in_s + (img * 32 + ic) * 84;
        #pragma unroll
        for (int a = 0; a < 2; a++) {
            #pragma unroll
            for (int bb = 0; bb < 2; bb++) {
                u64 xd = dup2(xs[(r0 - a) * 9 + (c0 - bb)]);
                int kk = (c + 2 * a) * 4 + (d + 2 * bb);
                const ulonglong2* wq = (const ulonglong2*)(w_s + (ic * 16 + kk) * 36);
                #pragma unroll
                for (int v = 0; v < 8; v++) {
                    ulonglong2 wv = wq[v];
                    fm2(acc[2 * v], xd, wv.x); fm2(acc[2 * v + 1], xd, wv.y);
                }
            }
        }
    }
    #pragma unroll
    for (int j = 0; j < 16; j++) {
        float lo, hi; up2(acc[j], lo, hi);
        g_u2[(size_t)((b0 + img) * 32 + 2 * j)     * 196 + p] = fmaxf(lo, 0.f);
        g_u2[(size_t)((b0 + img) * 32 + 2 * j + 1) * 196 + p] = fmaxf(hi, 0.f);
    }
}

// ---------------- deconv3: 2 imgs/block, thread = 1x4 output run (unchanged) ----------------
__global__ void deconv3_k(const float* __restrict__ w, const float* __restrict__ bias,
                          float* __restrict__ out) {
    extern __shared__ float sm[];
    float* in_s = sm;                    // 2*32*256 = 16384
    u64*   wpk  = (u64*)(sm + 16384);    // 256 u64
    int b0 = blockIdx.x * 2, tid = threadIdx.x, nt = blockDim.x;
    float4* z4 = (float4*)in_s;
    for (int i = tid; i < 4096; i += nt) z4[i] = make_float4(0.f, 0.f, 0.f, 0.f);
    for (int i = tid; i < 256; i += nt) {
        int t = i & 1, rest = i >> 1;
        int ic = rest & 31, ky = rest >> 5;
        wpk[(ky * 32 + ic) * 2 + t] = pk2(w[ic * 16 + ky * 4 + 2 * t + 1], w[ic * 16 + ky * 4 + 2 * t]);
    }
    __syncthreads();
    for (int i = tid; i < 2 * 6272; i += nt) {
        int img = i / 6272, r = i % 6272;
        int ic = r / 196, q = r % 196, y = q / 14, xx = q % 14;
        in_s[(img * 32 + ic) * 256 + (y + 1) * 16 + (xx + 1)] = g_u2[(size_t)(b0 + img) * 6272 + r];
    }
    __syncthreads();
    if (tid >= 392) return;
    int img = tid / 196, q = tid % 196;
    int oy = q / 7, t = q % 7;
    int mm = 2 * t;
    int c = (oy + 1) & 1;
    int r0 = ((oy + 1 - c) >> 1) + 1;
    float b0v = bias[0];
    u64 p1 = pk2(b0v, b0v), p2 = pk2(0.f, 0.f);
    for (int ic = 0; ic < 32; ic++) {
        const float* xs = in_s + (img * 32 + ic) * 256;
        const float* row0 = xs + r0 * 16 + mm;
        const float* row1 = row0 - 16;
        float i00 = row0[0], i01 = row0[1], i02 = row0[2], i03 = row0[3];
        float i10 = row1[0], i11 = row1[1], i12 = row1[2], i13 = row1[3];
        u64 q01a = pk2(i00, i01), q12a = pk2(i01, i02), q23a = pk2(i02, i03);
        u64 q01b = pk2(i10, i11), q12b = pk2(i11, i12), q23b = pk2(i12, i13);
        ulonglong2 wa = *(const ulonglong2*)&wpk[(c * 32 + ic) * 2];
        ulonglong2 wb = *(const ulonglong2*)&wpk[((c + 2) * 32 + ic) * 2];
        fm2(p1, q12a, wa.x); fm2(p1, q01a, wa.y);
        fm2(p2, q23a, wa.x); fm2(p2, q12a, wa.y);
        fm2(p1, q12b, wb.x); fm2(p1, q01b, wb.y);
        fm2(p2, q23b, wb.x); fm2(p2, q12b, wb.y);
    }
    float v0, v1, v2, v3;
    up2(p1, v0, v1); up2(p2, v2, v3);
    v2 += b0v; v3 += b0v;
    size_t ob = (size_t)(b0 + img) * 784 + oy * 28 + 4 * t;
    out[ob]     = 1.0f / (1.0f + expf(-v0));
    out[ob + 1] = 1.0f / (1.0f + expf(-v1));
    out[ob + 2] = 1.0f / (1.0f + expf(-v2));
    out[ob + 3] = 1.0f / (1.0f + expf(-v3));
}

// ---------------- launch ----------------
extern "C" void kernel_launch(void* const* d_in, const int* in_sizes, int n_in,
                              void* d_out, int out_size) {
    const float* x     = (const float*)d_in[0];
    const float* eps   = (const float*)d_in[1];
    const float* w_c1  = (const float*)d_in[2];
    const float* b_c1  = (const float*)d_in[3];
    const float* w_c2  = (const float*)d_in[4];
    const float* b_c2  = (const float*)d_in[5];
    const float* w_c3  = (const float*)d_in[6];
    const float* b_c3  = (const float*)d_in[7];
    const float* w_fc1 = (const float*)d_in[8];
    const float* b_fc1 = (const float*)d_in[9];
    const float* w_mu  = (const float*)d_in[10];
    const float* b_mu  = (const float*)d_in[11];
    const float* w_ls  = (const float*)d_in[12];
    const float* b_ls  = (const float*)d_in[13];
    const float* w_fc2 = (const float*)d_in[14];
    const float* b_fc2 = (const float*)d_in[15];
    const float* w_fc3 = (const float*)d_in[16];
    const float* b_fc3 = (const float*)d_in[17];
    const float* w_d1  = (const float*)d_in[18];
    const float* b_d1  = (const float*)d_in[19];
    const float* w_d2  = (const float*)d_in[20];
    const float* b_d2  = (const float*)d_in[21];
    const float* w_d3  = (const float*)d_in[22];
    const float* b_d3  = (const float*)d_in[23];
    float* out = (float*)d_out;

    cudaFuncSetAttribute(conv2_k,   cudaFuncAttributeMaxDynamicSharedMemorySize, 221184);
    cudaFuncSetAttribute(conv3_k,   cudaFuncAttributeMaxDynamicSharedMemorySize, 207360);
    cudaFuncSetAttribute(deconv1_k, cudaFuncAttributeMaxDynamicSharedMemorySize, 103424);
    cudaFuncSetAttribute(deconv2_k, cudaFuncAttributeMaxDynamicSharedMemorySize, 95232);
    cudaFuncSetAttribute(deconv3_k, cudaFuncAttributeMaxDynamicSharedMemorySize, 69632);

    float *p_h3, *p_hf, *p_f2, *p_f3;
    cudaGetSymbolAddress((void**)&p_h3, g_h3);
    cudaGetSymbolAddress((void**)&p_hf, g_hf);
    cudaGetSymbolAddress((void**)&p_f2, g_f2);
    cudaGetSymbolAddress((void**)&p_f3, g_f3);

    conv1_k<<<NB, 256, (784 + 512) * 4>>>(x, w_c1, b_c1);
    conv2_k<<<NB / 4, 416, 221184>>>(w_c2, b_c2);
    conv3_k<<<(NB + 11) / 12, 384, 207360>>>(w_c3, b_c3);
    gemm_k<<<dim3(256 / 64, NB / 32), 128>>>(p_h3, w_fc1, b_fc1, p_hf, NB, 256, 1024, 1);
    latent_k<<<(NB * 20 + 255) / 256, 256>>>(w_mu, b_mu, w_ls, b_ls, eps, out);
    fc2_k<<<(NB * 256 + 255) / 256, 256>>>(w_fc2, b_fc2);
    gemm_k<<<dim3(1024 / 64, NB / 32), 128>>>(p_f2, w_fc3, b_fc3, p_f3, NB, 1024, 256, 1);
    deconv1_k<<<(NB + 4) / 5, 512, 103424>>>(w_d1, b_d1);
    deconv2_k<<<NB / 2, 416, 95232>>>(w_d2, b_d2);
    deconv3_k<<<NB / 2, 416, 69632>>>(w_d3, b_d3, out);
}